// round 12
// baseline (speedup 1.0000x reference)
#include <cuda_runtime.h>
#include <cuda_fp16.h>

#define B_SZ    512
#define FEATS   30
#define NNZ     (B_SZ * FEATS)
#define FT_OUT  512
#define N_FEAT  40960
#define N_VFEAT 640
#define KPAIRS  (FT_OUT / 2)    // 256

#define NCHUNK      4
#define CHUNK_ITERS 5                      // stream iterations per chunk
#define CHUNK_COLS  (CHUNK_ITERS * 512 * 4)  // 10240 columns per chunk

// Packed indices, feature-major: g_packed[f*B + b] = stm_col | (nstm_col<<16)
__device__ unsigned g_packed[NNZ];
__device__ __half   g_vals[NNZ];          // values, feature-major, fp16
// Partial outputs, [k][b] layout -> coalesced stores and reads. 1 MB.
__device__ float    g_partial[FT_OUT * B_SZ];

// Dynamic smem: __half2 sft2[N_FEAT] (pair-interleaved fused table, 160 KB),
//               __half2 sfft2[N_VFEAT] (2.5 KB)
#define SMEM_BYTES ((N_FEAT + N_VFEAT) * 4)

static __device__ __forceinline__ unsigned h2u(__half2 h) {
    return *reinterpret_cast<unsigned*>(&h);
}
static __device__ __forceinline__ __half2 u2h(unsigned u) {
    return *reinterpret_cast<__half2*>(&u);
}

// ---------------------------------------------------------------------------
// Kernel 0: prepass. Pack cols into u32, values into fp16, feature-major.
// Triggers PDL completion immediately so the main kernel streams concurrently.
// ---------------------------------------------------------------------------
__global__ void __launch_bounds__(256) pack_idx_kernel(
    const int*   __restrict__ stm_idx,    // [2, NNZ]; cols at offset NNZ
    const int*   __restrict__ nstm_idx,   // [2, NNZ]
    const float* __restrict__ values)     // [NNZ]
{
    cudaTriggerProgrammaticLaunchCompletion();

    const int e = blockIdx.x * 256 + threadIdx.x;
    if (e >= NNZ) return;
    const int b = e / FEATS;
    const int f = e % FEATS;
    const unsigned cs = (unsigned)stm_idx [NNZ + e];
    const unsigned cn = (unsigned)nstm_idx[NNZ + e];
    const int dst = f * B_SZ + b;
    g_packed[dst] = cs | (cn << 16);
    g_vals[dst]   = __float2half(values[e]);
}

// ---------------------------------------------------------------------------
// Kernel 1: one CTA per k-PAIR (256 CTAs, 512 threads, 1 CTA/SM, 163KB smem).
// Software-pipelined: the table is built in 4 chunks; chunk j+1's GMEM loads
// (register-staged, no smem) fly while the compute pass over chunk j's
// lookups runs on the shared-memory crossbar. Indices/values are preloaded
// into registers once (no repeated L2 index traffic).
// ---------------------------------------------------------------------------
__global__ void __launch_bounds__(512, 1) halfkp_pair_kernel(
    const float* __restrict__ ft_w,      // [512, 40960]
    const float* __restrict__ ft_b,      // [512]
    const float* __restrict__ fft_w,     // [512, 640]
    const float* __restrict__ fft_b,     // [512]
    const float* __restrict__ out_w)     // [1, 1024]
{
    cudaTriggerProgrammaticLaunchCompletion();   // let reduce kernel launch

    extern __shared__ char smem_raw[];
    __half2* sft2  = reinterpret_cast<__half2*>(smem_raw);   // [N_FEAT]
    __half2* sfft2 = sft2 + N_FEAT;                          // [N_VFEAT]

    const int kp = blockIdx.x;
    const int k0 = 2 * kp;
    const int t  = threadIdx.x;

    // ---- Phase A: fft rows pair-interleaved into smem ----
    if (t < N_VFEAT / 4) {   // 160 threads, one float4 per row each
        float4 a = __ldg(reinterpret_cast<const float4*>(
                             fft_w + (size_t)k0 * N_VFEAT) + t);
        float4 b = __ldg(reinterpret_cast<const float4*>(
                             fft_w + (size_t)(k0 + 1) * N_VFEAT) + t);
        uint4 p;
        p.x = h2u(__floats2half2_rn(a.x, b.x));
        p.y = h2u(__floats2half2_rn(a.y, b.y));
        p.z = h2u(__floats2half2_rn(a.z, b.z));
        p.w = h2u(__floats2half2_rn(a.w, b.w));
        reinterpret_cast<uint4*>(sfft2)[t] = p;
    }
    __syncthreads();

    // Register cache of the 5 distinct fused-fft groups this thread needs:
    // global stream iter ii uses residue ii % 5.
    uint4 fc[CHUNK_ITERS];
    #pragma unroll
    for (int j = 0; j < CHUNK_ITERS; j++) {
        const int m = (4 * t + 128 * j) % N_VFEAT;   // multiple of 4
        fc[j] = *reinterpret_cast<const uint4*>(sfft2 + m);
    }

    const float4* r0 = reinterpret_cast<const float4*>(ft_w + (size_t)k0 * N_FEAT);
    const float4* r1 = reinterpret_cast<const float4*>(ft_w + (size_t)(k0 + 1) * N_FEAT);

    float4 s0[CHUNK_ITERS], s1[CHUNK_ITERS];         // LDG staging (40 regs)

    auto stage = [&](int j) {
        #pragma unroll
        for (int i = 0; i < CHUNK_ITERS; i++) {
            const int idx = t + (j * CHUNK_ITERS + i) * 512;
            s0[i] = __ldg(r0 + idx);
            s1[i] = __ldg(r1 + idx);
        }
    };
    auto commit = [&](int j) {   // convert + fuse + STS (waits on staged LDGs)
        #pragma unroll
        for (int i = 0; i < CHUNK_ITERS; i++) {
            const int c = (t + (j * CHUNK_ITERS + i) * 512) * 4;
            const uint4 f = fc[i];
            uint4 p;
            p.x = h2u(__hadd2(__floats2half2_rn(s0[i].x, s1[i].x), u2h(f.x)));
            p.y = h2u(__hadd2(__floats2half2_rn(s0[i].y, s1[i].y), u2h(f.y)));
            p.z = h2u(__hadd2(__floats2half2_rn(s0[i].z, s1[i].z), u2h(f.z)));
            p.w = h2u(__hadd2(__floats2half2_rn(s0[i].w, s1[i].w), u2h(f.w)));
            *reinterpret_cast<uint4*>(sft2 + c) = p;
        }
    };

    // ---- Stage chunk 0, then satisfy the pack dependency & preload idx ----
    stage(0);
    cudaGridDependencySynchronize();     // pack prepass complete

    unsigned pk[FEATS];
    __half   vl[FEATS];
    #pragma unroll
    for (int f = 0; f < FEATS; f++) {
        pk[f] = __ldg(g_packed + f * B_SZ + t);      // lane-consecutive
        vl[f] = g_vals[f * B_SZ + t];
    }

    commit(0);
    __syncthreads();                     // chunk 0 table visible

    float2 accs = make_float2(0.f, 0.f);
    float2 accn = make_float2(0.f, 0.f);

    auto pass = [&](int j) {             // lookups with column in chunk j
        const unsigned lo = j * CHUNK_COLS;
        #pragma unroll
        for (int f = 0; f < FEATS; f++) {
            const unsigned cs = pk[f] & 0xFFFFu;
            const unsigned cn = pk[f] >> 16;
            const float vf = __half2float(vl[f]);
            if (cs - lo < CHUNK_COLS) {
                float2 w = __half22float2(sft2[cs]);
                accs.x = fmaf(vf, w.x, accs.x);
                accs.y = fmaf(vf, w.y, accs.y);
            }
            if (cn - lo < CHUNK_COLS) {
                float2 w = __half22float2(sft2[cn]);
                accn.x = fmaf(vf, w.x, accn.x);
                accn.y = fmaf(vf, w.y, accn.y);
            }
        }
    };

    // ---- Pipelined chunks: stage(j+1) LDGs fly under pass(j) ----
    #pragma unroll
    for (int j = 1; j < NCHUNK; j++) {
        stage(j);                         // LDG, no waits
        pass(j - 1);                      // crossbar work overlaps LDG flight
        commit(j);                        // waits staged data, STS
        __syncthreads();
    }
    pass(NCHUNK - 1);

    // ---- Epilogue: bias + clip + out_w partials for k0 and k1 ----
    const float b0 = __ldg(ft_b + k0)     + __ldg(fft_b + k0);
    const float b1 = __ldg(ft_b + k0 + 1) + __ldg(fft_b + k0 + 1);
    const float w0 = __ldg(out_w + k0);
    const float w1 = __ldg(out_w + k0 + 1);
    const float u0 = __ldg(out_w + FT_OUT + k0);
    const float u1 = __ldg(out_w + FT_OUT + k0 + 1);

    g_partial[(size_t)k0 * B_SZ + t] =
        w0 * __saturatef(accs.x + b0) + u0 * __saturatef(accn.x + b0);
    g_partial[(size_t)(k0 + 1) * B_SZ + t] =
        w1 * __saturatef(accs.y + b1) + u1 * __saturatef(accn.y + b1);
}

// ---------------------------------------------------------------------------
// Kernel 2: sum the 512 k-partials per batch row ([k][b], coalesced along b),
// add out_b, sigmoid. 512 threads: 16 k-groups x 32 b-lanes. Deterministic.
// ---------------------------------------------------------------------------
__global__ void __launch_bounds__(512) halfkp_reduce_kernel(
    const float* __restrict__ out_b,
    float*       __restrict__ out)       // [512]
{
    const int tx = threadIdx.x & 31;     // batch lane
    const int ty = threadIdx.x >> 5;     // k group (0..15), 32 k's each
    const int b  = blockIdx.x * 32 + tx;

    cudaGridDependencySynchronize();     // wait for main kernel's g_partial

    float s = 0.f;
    #pragma unroll 8
    for (int i = 0; i < FT_OUT / 16; i++)
        s += g_partial[(ty * (FT_OUT / 16) + i) * B_SZ + b];

    __shared__ float red[16][33];
    red[ty][tx] = s;
    __syncthreads();

    if (ty == 0) {
        float tot = __ldg(out_b);
        #pragma unroll
        for (int j = 0; j < 16; j++) tot += red[j][tx];
        out[b] = 1.0f / (1.0f + expf(-tot));
    }
}

// ---------------------------------------------------------------------------
extern "C" void kernel_launch(void* const* d_in, const int* in_sizes, int n_in,
                              void* d_out, int out_size) {
    const int*   stm_idx  = (const int*)  d_in[0];
    const int*   nstm_idx = (const int*)  d_in[1];
    const float* values   = (const float*)d_in[2];
    const float* ft_w     = (const float*)d_in[3];
    const float* ft_b     = (const float*)d_in[4];
    const float* fft_w    = (const float*)d_in[5];
    const float* fft_b    = (const float*)d_in[6];
    const float* out_w    = (const float*)d_in[7];
    const float* out_b    = (const float*)d_in[8];
    float*       out      = (float*)d_out;

    (void)in_sizes; (void)n_in; (void)out_size;

    cudaFuncSetAttribute(halfkp_pair_kernel,
                         cudaFuncAttributeMaxDynamicSharedMemorySize, SMEM_BYTES);

    pack_idx_kernel<<<(NNZ + 255) / 256, 256>>>(stm_idx, nstm_idx, values);

    // Main kernel with PDL: overlaps with the pack kernel.
    {
        cudaLaunchConfig_t cfg = {};
        cfg.gridDim          = dim3(KPAIRS);
        cfg.blockDim         = dim3(512);
        cfg.dynamicSmemBytes = SMEM_BYTES;
        cfg.stream           = 0;
        cudaLaunchAttribute at[1];
        at[0].id = cudaLaunchAttributeProgrammaticStreamSerialization;
        at[0].val.programmaticStreamSerializationAllowed = 1;
        cfg.attrs    = at;
        cfg.numAttrs = 1;
        cudaLaunchKernelEx(&cfg, halfkp_pair_kernel,
                           ft_w, ft_b, fft_w, fft_b, out_w);
    }

    // Reduce with PDL: launches early, parks in grid-sync.
    {
        cudaLaunchConfig_t cfg = {};
        cfg.gridDim  = dim3(B_SZ / 32);
        cfg.blockDim = dim3(512);
        cfg.stream   = 0;
        cudaLaunchAttribute at[1];
        at[0].id = cudaLaunchAttributeProgrammaticStreamSerialization;
        at[0].val.programmaticStreamSerializationAllowed = 1;
        cfg.attrs    = at;
        cfg.numAttrs = 1;
        cudaLaunchKernelEx(&cfg, halfkp_reduce_kernel, out_b, out);
    }
}

// round 13
// speedup vs baseline: 2.2128x; 2.2128x over previous
#include <cuda_runtime.h>
#include <cuda_fp16.h>

#define B_SZ    512
#define FEATS   30
#define NNZ     (B_SZ * FEATS)
#define FT_OUT  512
#define N_FEAT  40960
#define N_VFEAT 640
#define KPAIRS  (FT_OUT / 2)    // 256

// Packed indices, feature-major: g_packed[f*B + b] = stm_col | (nstm_col<<16)
__device__ unsigned g_packed[NNZ];
__device__ __half   g_vals[NNZ];          // values, feature-major, fp16
// Partial outputs, [k][b] layout -> coalesced stores and reads. 1 MB.
__device__ float    g_partial[FT_OUT * B_SZ];

// Dynamic smem: __half2 sft2[N_FEAT] (pair-interleaved fused table, 160 KB),
//               __half2 sfft2[N_VFEAT] (2.5 KB)
#define SMEM_BYTES ((N_FEAT + N_VFEAT) * 4)

static __device__ __forceinline__ unsigned h2u(__half2 h) {
    return *reinterpret_cast<unsigned*>(&h);
}
static __device__ __forceinline__ __half2 u2h(unsigned u) {
    return *reinterpret_cast<__half2*>(&u);
}

// ---------------------------------------------------------------------------
// Kernel 0: prepass. Pack cols into u32, values into fp16, feature-major.
// Triggers PDL completion immediately so the main kernel streams concurrently.
// ---------------------------------------------------------------------------
__global__ void __launch_bounds__(256) pack_idx_kernel(
    const int*   __restrict__ stm_idx,    // [2, NNZ]; cols at offset NNZ
    const int*   __restrict__ nstm_idx,   // [2, NNZ]
    const float* __restrict__ values)     // [NNZ]
{
    cudaTriggerProgrammaticLaunchCompletion();

    const int e = blockIdx.x * 256 + threadIdx.x;
    if (e >= NNZ) return;
    const int b = e / FEATS;
    const int f = e % FEATS;
    const unsigned cs = (unsigned)stm_idx [NNZ + e];
    const unsigned cn = (unsigned)nstm_idx[NNZ + e];
    const int dst = f * B_SZ + b;
    g_packed[dst] = cs | (cn << 16);
    g_vals[dst]   = __float2half(values[e]);
}

// ---------------------------------------------------------------------------
// Kernel 1: one CTA per k-PAIR (256 CTAs, 512 threads, 1 CTA/SM, 163KB smem).
// Phase A: fft_w rows {k0, k0+1} -> smem, pair-interleaved half2.
// Phase B: stream ft_w rows {k0, k0+1}; sft2[c] = (ft[k0][c]+fft[k0][c%640],
//          ft[k1][c]+fft[k1][c%640]) as one half2. fft offsets have period 5
//          in the stream loop -> register-cached uint4 pairs.
// (PDL grid sync before Phase C.)
// Phase C: thread t = batch row t. All 30 packed-index/value loads issued in
//          ONE batch (full MLP), then 30 fused lookup groups: one random
//          LDS.32 per (feature, side) serves BOTH k's of the pair.
// ---------------------------------------------------------------------------
__global__ void __launch_bounds__(512, 1) halfkp_pair_kernel(
    const float* __restrict__ ft_w,      // [512, 40960]
    const float* __restrict__ ft_b,      // [512]
    const float* __restrict__ fft_w,     // [512, 640]
    const float* __restrict__ fft_b,     // [512]
    const float* __restrict__ out_w)     // [1, 1024]
{
    cudaTriggerProgrammaticLaunchCompletion();   // let reduce kernel launch

    extern __shared__ char smem_raw[];
    __half2* sft2  = reinterpret_cast<__half2*>(smem_raw);   // [N_FEAT]
    __half2* sfft2 = sft2 + N_FEAT;                          // [N_VFEAT]

    const int kp = blockIdx.x;
    const int k0 = 2 * kp;
    const int t  = threadIdx.x;

    // ---- Phase A: fft rows pair-interleaved ----
    if (t < N_VFEAT / 4) {   // 160 threads, one float4 per row each
        float4 a = __ldg(reinterpret_cast<const float4*>(
                             fft_w + (size_t)k0 * N_VFEAT) + t);
        float4 b = __ldg(reinterpret_cast<const float4*>(
                             fft_w + (size_t)(k0 + 1) * N_VFEAT) + t);
        uint4 p;
        p.x = h2u(__floats2half2_rn(a.x, b.x));
        p.y = h2u(__floats2half2_rn(a.y, b.y));
        p.z = h2u(__floats2half2_rn(a.z, b.z));
        p.w = h2u(__floats2half2_rn(a.w, b.w));
        reinterpret_cast<uint4*>(sfft2)[t] = p;
    }
    __syncthreads();

    // ---- Phase B: stream both rows, fuse fft, store pair-interleaved ----
    {
        // fft offset m_i = (4t + 2048 i) % 640 has period 5 (2048%640=128).
        // Cache the 5 distinct 16B sfft2 groups in registers.
        uint4 fc[5];
        #pragma unroll
        for (int j = 0; j < 5; j++) {
            const int m = (4 * t + 128 * j) % N_VFEAT;   // multiple of 4
            fc[j] = *reinterpret_cast<const uint4*>(sfft2 + m);
        }

        const float4* r0 = reinterpret_cast<const float4*>(
                               ft_w + (size_t)k0 * N_FEAT);
        const float4* r1 = reinterpret_cast<const float4*>(
                               ft_w + (size_t)(k0 + 1) * N_FEAT);
        #pragma unroll
        for (int i = 0; i < N_FEAT / 4 / 512; i++) {     // 20 iterations
            const int idx = t + i * 512;
            const int c   = idx * 4;                      // half2 column
            const uint4 f = fc[i % 5];                    // static per unroll
            float4 a = __ldg(r0 + idx);
            float4 b = __ldg(r1 + idx);
            uint4 p;
            p.x = h2u(__hadd2(__floats2half2_rn(a.x, b.x), u2h(f.x)));
            p.y = h2u(__hadd2(__floats2half2_rn(a.y, b.y), u2h(f.y)));
            p.z = h2u(__hadd2(__floats2half2_rn(a.z, b.z), u2h(f.z)));
            p.w = h2u(__hadd2(__floats2half2_rn(a.w, b.w), u2h(f.w)));
            *reinterpret_cast<uint4*>(sft2 + c) = p;      // STS.128 coalesced
        }
    }
    __syncthreads();

    // PDL: packed index data must be complete (and visible) before Phase C.
    cudaGridDependencySynchronize();

    // Prefetch epilogue scalars early (independent; consumed at the end).
    const float b0 = __ldg(ft_b + k0)     + __ldg(fft_b + k0);
    const float b1 = __ldg(ft_b + k0 + 1) + __ldg(fft_b + k0 + 1);
    const float w0 = __ldg(out_w + k0);
    const float w1 = __ldg(out_w + k0 + 1);
    const float u0 = __ldg(out_w + FT_OUT + k0);
    const float u1 = __ldg(out_w + FT_OUT + k0 + 1);

    // ---- Phase C: thread t = batch row t; one LDS.32 serves both k's ----
    // All index/value loads in one batch -> full MLP, no chunk-boundary stalls.
    unsigned pk[FEATS];
    __half   vl[FEATS];
    #pragma unroll
    for (int f = 0; f < FEATS; f++) {
        const int idx = f * B_SZ + t;                     // lane-consecutive
        pk[f] = __ldg(g_packed + idx);
        vl[f] = g_vals[idx];
    }

    float2 accs = make_float2(0.f, 0.f);
    float2 accn = make_float2(0.f, 0.f);

    #pragma unroll
    for (int f = 0; f < FEATS; f++) {
        const float vf = __half2float(vl[f]);
        float2 ws = __half22float2(sft2[pk[f] & 0xFFFFu]);
        float2 wn = __half22float2(sft2[pk[f] >> 16]);
        accs.x = fmaf(vf, ws.x, accs.x);
        accs.y = fmaf(vf, ws.y, accs.y);
        accn.x = fmaf(vf, wn.x, accn.x);
        accn.y = fmaf(vf, wn.y, accn.y);
    }

    // ---- Epilogue: bias + clip + out_w partials for k0 and k1 ----
    g_partial[(size_t)k0 * B_SZ + t] =
        w0 * __saturatef(accs.x + b0) + u0 * __saturatef(accn.x + b0);
    g_partial[(size_t)(k0 + 1) * B_SZ + t] =
        w1 * __saturatef(accs.y + b1) + u1 * __saturatef(accn.y + b1);
}

// ---------------------------------------------------------------------------
// Kernel 2: sum the 512 k-partials per batch row ([k][b], coalesced along b),
// add out_b, sigmoid. 512 threads: 16 k-groups x 32 b-lanes. Deterministic
// fixed-order summation. PDL-parked until the main kernel completes.
// ---------------------------------------------------------------------------
__global__ void __launch_bounds__(512) halfkp_reduce_kernel(
    const float* __restrict__ out_b,
    float*       __restrict__ out)       // [512]
{
    const int tx = threadIdx.x & 31;     // batch lane
    const int ty = threadIdx.x >> 5;     // k group (0..15), 32 k's each
    const int b  = blockIdx.x * 32 + tx;

    cudaGridDependencySynchronize();     // wait for main kernel's g_partial

    float s = 0.f;
    #pragma unroll 8
    for (int i = 0; i < FT_OUT / 16; i++)
        s += g_partial[(ty * (FT_OUT / 16) + i) * B_SZ + b];

    __shared__ float red[16][33];
    red[ty][tx] = s;
    __syncthreads();

    if (ty == 0) {
        float tot = __ldg(out_b);
        #pragma unroll
        for (int j = 0; j < 16; j++) tot += red[j][tx];
        out[b] = 1.0f / (1.0f + expf(-tot));
    }
}

// ---------------------------------------------------------------------------
extern "C" void kernel_launch(void* const* d_in, const int* in_sizes, int n_in,
                              void* d_out, int out_size) {
    const int*   stm_idx  = (const int*)  d_in[0];
    const int*   nstm_idx = (const int*)  d_in[1];
    const float* values   = (const float*)d_in[2];
    const float* ft_w     = (const float*)d_in[3];
    const float* ft_b     = (const float*)d_in[4];
    const float* fft_w    = (const float*)d_in[5];
    const float* fft_b    = (const float*)d_in[6];
    const float* out_w    = (const float*)d_in[7];
    const float* out_b    = (const float*)d_in[8];
    float*       out      = (float*)d_out;

    (void)in_sizes; (void)n_in; (void)out_size;

    cudaFuncSetAttribute(halfkp_pair_kernel,
                         cudaFuncAttributeMaxDynamicSharedMemorySize, SMEM_BYTES);

    pack_idx_kernel<<<(NNZ + 255) / 256, 256>>>(stm_idx, nstm_idx, values);

    // Main kernel with PDL: overlaps with the pack kernel.
    {
        cudaLaunchConfig_t cfg = {};
        cfg.gridDim          = dim3(KPAIRS);
        cfg.blockDim         = dim3(512);
        cfg.dynamicSmemBytes = SMEM_BYTES;
        cfg.stream           = 0;
        cudaLaunchAttribute at[1];
        at[0].id = cudaLaunchAttributeProgrammaticStreamSerialization;
        at[0].val.programmaticStreamSerializationAllowed = 1;
        cfg.attrs    = at;
        cfg.numAttrs = 1;
        cudaLaunchKernelEx(&cfg, halfkp_pair_kernel,
                           ft_w, ft_b, fft_w, fft_b, out_w);
    }

    // Reduce with PDL: launches early, parks in grid-sync.
    {
        cudaLaunchConfig_t cfg = {};
        cfg.gridDim  = dim3(B_SZ / 32);
        cfg.blockDim = dim3(512);
        cfg.stream   = 0;
        cudaLaunchAttribute at[1];
        at[0].id = cudaLaunchAttributeProgrammaticStreamSerialization;
        at[0].val.programmaticStreamSerializationAllowed = 1;
        cfg.attrs    = at;
        cfg.numAttrs = 1;
        cudaLaunchKernelEx(&cfg, halfkp_reduce_kernel, out_b, out);
    }
}